// round 15
// baseline (speedup 1.0000x reference)
#include <cuda_runtime.h>
#include <cuda_bf16.h>
#include <mma.h>
#include <math.h>
#include <stddef.h>

using namespace nvcuda;

#define S 4096
#define H 256
#define NH 6
#define G3 768
#define EPS 1e-5f

// ---------------- scratch (static device arrays; no allocation) ----------------
__device__ float g_x[S * H];
__device__ float g_q[NH * S * H];
__device__ float g_k[NH * S * H];
__device__ float g_v[NH * S * H];
__device__ float g_o[NH * S * H];
__device__ float g_ypre[S * H];
__device__ float g_y[S * H];
__device__ float g_gi[S * G3];

// ---------------- embedding gather ----------------
__global__ void embed_kernel(const int* __restrict__ tokens,
                             const float* __restrict__ emb) {
    int s = blockIdx.x;
    int tok = tokens[s];
    const float4* src = (const float4*)(emb + (size_t)tok * H);
    float4* dst = (float4*)(g_x + (size_t)s * H);
    dst[threadIdx.x] = src[threadIdx.x];
}

// ---------------- WMMA tf32 QKV GEMM, all 3 projections in one launch --------
#define LDG_ 68
__global__ __launch_bounds__(256) void gemm_qkv(const float* __restrict__ A,
                                                const float* __restrict__ Wq,
                                                const float* __restrict__ bq,
                                                const float* __restrict__ Wk,
                                                const float* __restrict__ bk,
                                                const float* __restrict__ Wv,
                                                const float* __restrict__ bv,
                                                float* __restrict__ Cq,
                                                float* __restrict__ Ck,
                                                float* __restrict__ Cv) {
    __shared__ float As[64 * LDG_];
    __shared__ float Bs[64 * LDG_];
    int tid = threadIdx.x;
    int warp = tid >> 5;
    int wm = warp & 3;
    int wn = warp >> 2;
    int m0 = blockIdx.y * 64, n0 = blockIdx.x * 64;
    int z = blockIdx.z;
    int which = z / 6, zh = z - which * 6;
    const float* Bb = ((which == 0) ? Wq : (which == 1) ? Wk : Wv) +
                      (size_t)zh * 256 * 256;
    const float* bias = ((which == 0) ? bq : (which == 1) ? bk : bv) + zh * 256;
    float* C = ((which == 0) ? Cq : (which == 1) ? Ck : Cv);

    wmma::fragment<wmma::accumulator, 16, 16, 8, float> c[2];
    wmma::fill_fragment(c[0], 0.0f);
    wmma::fill_fragment(c[1], 0.0f);

    for (int k0 = 0; k0 < 256; k0 += 64) {
        const float* Asrc = A + k0;
        for (int i = tid; i < 64 * 16; i += 256) {
            int m = i >> 4, k4 = i & 15;
            float4 v = *(const float4*)(Asrc + (size_t)(m0 + m) * 256 + k4 * 4);
            *(float4*)(As + m * LDG_ + k4 * 4) = v;
        }
        for (int i = tid; i < 64 * 16; i += 256) {
            int kk = i >> 4, n4 = i & 15;
            float4 v = *(const float4*)(Bb + (size_t)(k0 + kk) * 256 + n0 + n4 * 4);
            *(float4*)(Bs + kk * LDG_ + n4 * 4) = v;
        }
        __syncthreads();

        wmma::fragment<wmma::matrix_a, 16, 16, 8, wmma::precision::tf32,
                       wmma::row_major> af;
        wmma::fragment<wmma::matrix_b, 16, 16, 8, wmma::precision::tf32,
                       wmma::row_major> bf;
#pragma unroll
        for (int k = 0; k < 8; k++) {
            wmma::load_matrix_sync(af, As + (wm * 16) * LDG_ + k * 8, LDG_);
#pragma unroll
            for (int e = 0; e < af.num_elements; e++)
                af.x[e] = wmma::__float_to_tf32(af.x[e]);
#pragma unroll
            for (int nf = 0; nf < 2; nf++) {
                wmma::load_matrix_sync(
                    bf, Bs + (k * 8) * LDG_ + wn * 32 + nf * 16, LDG_);
#pragma unroll
                for (int e = 0; e < bf.num_elements; e++)
                    bf.x[e] = wmma::__float_to_tf32(bf.x[e]);
                wmma::mma_sync(c[nf], af, bf, c[nf]);
            }
        }
        __syncthreads();
    }

#pragma unroll
    for (int nf = 0; nf < 2; nf++)
        wmma::store_matrix_sync(As + (wm * 16) * LDG_ + wn * 32 + nf * 16,
                                c[nf], LDG_, wmma::mem_row_major);
    __syncthreads();

    for (int i = tid; i < 64 * 64; i += 256) {
        int m = i >> 6, n = i & 63;
        int gm = m0 + m, gn = n0 + n;
        float v = As[m * LDG_ + n] + bias[gn];
        C[(size_t)zh * S * 256 + (size_t)gm * 256 + gn] = v;
    }
}

// ---------------- WMMA tf32 out-proj (+residual) -----------------------------
__global__ __launch_bounds__(256) void gemm_op(const float* __restrict__ A,
                                               const float* __restrict__ B,
                                               const float* __restrict__ bias,
                                               const float* __restrict__ resid,
                                               float* __restrict__ C) {
    __shared__ float As[64 * LDG_];
    __shared__ float Bs[64 * LDG_];
    int tid = threadIdx.x;
    int warp = tid >> 5;
    int wm = warp & 3;
    int wn = warp >> 2;
    int m0 = blockIdx.y * 64, n0 = blockIdx.x * 64;

    wmma::fragment<wmma::accumulator, 16, 16, 8, float> c[2];
    wmma::fill_fragment(c[0], 0.0f);
    wmma::fill_fragment(c[1], 0.0f);

    for (int k0 = 0; k0 < 1536; k0 += 64) {
        const float* Asrc = A + (size_t)(k0 >> 8) * (S * 256) + (k0 & 255);
        for (int i = tid; i < 64 * 16; i += 256) {
            int m = i >> 4, k4 = i & 15;
            float4 v = *(const float4*)(Asrc + (size_t)(m0 + m) * 256 + k4 * 4);
            *(float4*)(As + m * LDG_ + k4 * 4) = v;
        }
        for (int i = tid; i < 64 * 16; i += 256) {
            int kk = i >> 4, n4 = i & 15;
            float4 v = *(const float4*)(B + (size_t)(k0 + kk) * 256 + n0 + n4 * 4);
            *(float4*)(Bs + kk * LDG_ + n4 * 4) = v;
        }
        __syncthreads();

        wmma::fragment<wmma::matrix_a, 16, 16, 8, wmma::precision::tf32,
                       wmma::row_major> af;
        wmma::fragment<wmma::matrix_b, 16, 16, 8, wmma::precision::tf32,
                       wmma::row_major> bf;
#pragma unroll
        for (int k = 0; k < 8; k++) {
            wmma::load_matrix_sync(af, As + (wm * 16) * LDG_ + k * 8, LDG_);
#pragma unroll
            for (int e = 0; e < af.num_elements; e++)
                af.x[e] = wmma::__float_to_tf32(af.x[e]);
#pragma unroll
            for (int nf = 0; nf < 2; nf++) {
                wmma::load_matrix_sync(
                    bf, Bs + (k * 8) * LDG_ + wn * 32 + nf * 16, LDG_);
#pragma unroll
                for (int e = 0; e < bf.num_elements; e++)
                    bf.x[e] = wmma::__float_to_tf32(bf.x[e]);
                wmma::mma_sync(c[nf], af, bf, c[nf]);
            }
        }
        __syncthreads();
    }

#pragma unroll
    for (int nf = 0; nf < 2; nf++)
        wmma::store_matrix_sync(As + (wm * 16) * LDG_ + wn * 32 + nf * 16,
                                c[nf], LDG_, wmma::mem_row_major);
    __syncthreads();

    for (int i = tid; i < 64 * 64; i += 256) {
        int m = i >> 6, n = i & 63;
        int gm = m0 + m, gn = n0 + n;
        float v = As[m * LDG_ + n] + bias[gn] + resid[(size_t)gm * 256 + gn];
        C[(size_t)gm * 256 + gn] = v;
    }
}

// ---------------- fp32 SIMT GEMM for gi = y @ W_ih^T + b_ih ------------------
__global__ __launch_bounds__(256) void gemm_gi(const float* __restrict__ A,
                                               const float* __restrict__ B,
                                               const float* __restrict__ bias,
                                               float* __restrict__ C) {
    __shared__ float As[64][65];
    __shared__ float Bs[64][65];
    int tid = threadIdx.x;
    int m0 = blockIdx.y * 64, n0 = blockIdx.x * 64;

    float acc[4][4];
#pragma unroll
    for (int i = 0; i < 4; i++)
#pragma unroll
        for (int j = 0; j < 4; j++) acc[i][j] = 0.f;

    int ty = tid >> 4, tx = tid & 15;

    for (int k0 = 0; k0 < 256; k0 += 64) {
#pragma unroll
        for (int i = 0; i < 16; i++) {
            int lin = i * 256 + tid;
            int m = lin >> 6, kk = lin & 63;
            As[m][kk] = A[(size_t)(m0 + m) * 256 + k0 + kk];
        }
#pragma unroll
        for (int i = 0; i < 16; i++) {
            int lin = i * 256 + tid;
            int n = lin >> 6, kk = lin & 63;
            Bs[kk][n] = B[(size_t)(n0 + n) * 256 + (k0 + kk)];
        }
        __syncthreads();
#pragma unroll 8
        for (int kk = 0; kk < 64; kk++) {
            float a[4], b[4];
#pragma unroll
            for (int i = 0; i < 4; i++) a[i] = As[ty * 4 + i][kk];
#pragma unroll
            for (int j = 0; j < 4; j++) b[j] = Bs[kk][tx * 4 + j];
#pragma unroll
            for (int i = 0; i < 4; i++)
#pragma unroll
                for (int j = 0; j < 4; j++) acc[i][j] += a[i] * b[j];
        }
        __syncthreads();
    }

#pragma unroll
    for (int i = 0; i < 4; i++) {
        int m = m0 + ty * 4 + i;
#pragma unroll
        for (int j = 0; j < 4; j++) {
            int n = n0 + tx * 4 + j;
            C[(size_t)m * 768 + n] = acc[i][j] + bias[n];
        }
    }
}

// ---------------- WMMA tf32 streaming attention ------------------------------
#define LDQ 268
#define LDP 76
__global__ __launch_bounds__(256) void attn_kernel(const float* __restrict__ Q,
                                                   const float* __restrict__ K,
                                                   const float* __restrict__ V,
                                                   float* __restrict__ O) {
    extern __shared__ float sm[];
    float* Qs = sm;
    float* Ks = Qs + 64 * LDQ;
    float* Vs = Ks + 64 * LDQ;
    float* Ps = Vs + 64 * LDQ;
    float* Ls = Ps + 64 * LDP;

    int h = blockIdx.y;
    int q0 = blockIdx.x * 64;
    int tid = threadIdx.x;
    int warp = tid >> 5;
    int wm = warp & 3;
    int wn = warp >> 2;

    const float* Qg = Q + ((size_t)h * S + q0) * H;
    const float* Kg = K + (size_t)h * S * H;
    const float* Vg = V + (size_t)h * S * H;

    for (int i = tid; i < 64 * 64; i += 256) {
        int q = i >> 6, d4 = i & 63;
        ((float4*)(Qs + q * LDQ))[d4] = ((const float4*)(Qg + (size_t)q * H))[d4];
    }

    wmma::fragment<wmma::accumulator, 16, 16, 8, float> o_frag[8];
#pragma unroll
    for (int f = 0; f < 8; f++) wmma::fill_fragment(o_frag[f], 0.0f);

    int lrow = tid >> 2;
    int lcol0 = (tid & 3) * 16;
    float l_part = 0.f;
    const float inv_scale = 0.0625f;

    for (int kt = 0; kt < S / 64; kt++) {
        __syncthreads();
        for (int i = tid; i < 64 * 64; i += 256) {
            int r = i >> 6, d4 = i & 63;
            ((float4*)(Ks + r * LDQ))[d4] =
                ((const float4*)(Kg + (size_t)(kt * 64 + r) * H))[d4];
            ((float4*)(Vs + r * LDQ))[d4] =
                ((const float4*)(Vg + (size_t)(kt * 64 + r) * H))[d4];
        }
        __syncthreads();

        {
            wmma::fragment<wmma::matrix_a, 16, 16, 8, wmma::precision::tf32,
                           wmma::row_major> af;
            wmma::fragment<wmma::matrix_b, 16, 16, 8, wmma::precision::tf32,
                           wmma::col_major> bf;
            wmma::fragment<wmma::accumulator, 16, 16, 8, float> c[2];
            wmma::fill_fragment(c[0], 0.0f);
            wmma::fill_fragment(c[1], 0.0f);
#pragma unroll 4
            for (int k = 0; k < 32; k++) {
                wmma::load_matrix_sync(af, Qs + (wm * 16) * LDQ + k * 8, LDQ);
#pragma unroll
                for (int e = 0; e < af.num_elements; e++)
                    af.x[e] = wmma::__float_to_tf32(af.x[e]);
#pragma unroll
                for (int nf = 0; nf < 2; nf++) {
                    wmma::load_matrix_sync(
                        bf, Ks + (wn * 32 + nf * 16) * LDQ + k * 8, LDQ);
#pragma unroll
                    for (int e = 0; e < bf.num_elements; e++)
                        bf.x[e] = wmma::__float_to_tf32(bf.x[e]);
                    wmma::mma_sync(c[nf], af, bf, c[nf]);
                }
            }
#pragma unroll
            for (int nf = 0; nf < 2; nf++)
                wmma::store_matrix_sync(
                    Ps + (wm * 16) * LDP + wn * 32 + nf * 16, c[nf], LDP,
                    wmma::mem_row_major);
        }
        __syncthreads();

        {
            float* pr = Ps + lrow * LDP + lcol0;
            float ssum = 0.f;
#pragma unroll
            for (int j = 0; j < 16; j++) {
                float e = __expf(pr[j] * inv_scale);
                pr[j] = e;
                ssum += e;
            }
            l_part += ssum;
        }
        __syncthreads();

        {
            wmma::fragment<wmma::matrix_a, 16, 16, 8, wmma::precision::tf32,
                           wmma::row_major> pa;
            wmma::fragment<wmma::matrix_b, 16, 16, 8, wmma::precision::tf32,
                           wmma::row_major> vb;
#pragma unroll
            for (int k = 0; k < 8; k++) {
                wmma::load_matrix_sync(pa, Ps + (wm * 16) * LDP + k * 8, LDP);
#pragma unroll
                for (int e = 0; e < pa.num_elements; e++)
                    pa.x[e] = wmma::__float_to_tf32(pa.x[e]);
#pragma unroll
                for (int nf = 0; nf < 8; nf++) {
                    wmma::load_matrix_sync(
                        vb, Vs + (k * 8) * LDQ + wn * 128 + nf * 16, LDQ);
#pragma unroll
                    for (int e = 0; e < vb.num_elements; e++)
                        vb.x[e] = wmma::__float_to_tf32(vb.x[e]);
                    wmma::mma_sync(o_frag[nf], pa, vb, o_frag[nf]);
                }
            }
        }
    }

    l_part += __shfl_xor_sync(0xffffffffu, l_part, 1);
    l_part += __shfl_xor_sync(0xffffffffu, l_part, 2);
    if ((tid & 3) == 0) Ls[lrow] = l_part;

#pragma unroll
    for (int nf = 0; nf < 8; nf++)
        wmma::store_matrix_sync(Qs + (wm * 16) * LDQ + wn * 128 + nf * 16,
                                o_frag[nf], LDQ, wmma::mem_row_major);
    __syncthreads();

    float* Og = O + ((size_t)h * S + q0) * H;
    for (int i = tid; i < 64 * 64; i += 256) {
        int q = i >> 6, d4 = i & 63;
        float inv_l = __frcp_rn(Ls[q]);
        float4 v = ((float4*)(Qs + q * LDQ))[d4];
        v.x *= inv_l; v.y *= inv_l; v.z *= inv_l; v.w *= inv_l;
        ((float4*)(Og + (size_t)q * H))[d4] = v;
    }
}

// ---------------- LayerNorm (one warp per row) ----------------
__global__ __launch_bounds__(256) void ln_kernel(const float* __restrict__ yin,
                                                 const float* __restrict__ g,
                                                 const float* __restrict__ b,
                                                 float* __restrict__ yout) {
    int row = blockIdx.x * 8 + (threadIdx.x >> 5);
    int lane = threadIdx.x & 31;
    const float* yr = yin + (size_t)row * H;
    float v[8], s = 0.f, sq = 0.f;
#pragma unroll
    for (int i = 0; i < 8; i++) {
        v[i] = yr[lane + i * 32];
        s += v[i];
        sq += v[i] * v[i];
    }
#pragma unroll
    for (int m = 16; m >= 1; m >>= 1) {
        s += __shfl_xor_sync(0xffffffffu, s, m);
        sq += __shfl_xor_sync(0xffffffffu, sq, m);
    }
    float mu = s * (1.f / H);
    float var = sq * (1.f / H) - mu * mu;
    float rstd = rsqrtf(var + EPS);
    float* yo = yout + (size_t)row * H;
#pragma unroll
    for (int i = 0; i < 8; i++) {
        int c = lane + i * 32;
        yo[c] = (v[i] - mu) * rstd * g[c] + b[c];
    }
}

// ---------------- GRU recurrence: collector-tree tx-spread exchange ----------
// R15 (RNN only vs R14): tx traffic spread over 4 group mbarriers per parity
// (sender warp w -> group w&3 on every CTA; 16 packets x 16B = 256B each), and
// the join is a collector tree: lane0 of warps 0..3 each waits ONE group mbar
// (parallel across warps — no intra-warp divergent multi-waits, the R13 bug),
// re-arms it, then arrives on a count-4 final mbar; everyone else waits only
// the final mbar. Receiver-side mbar tx processing parallelized 4x at the cost
// of one wakeup+arrive hop.
#define RB 8
#define RT 256

__device__ __forceinline__ unsigned int smem_u32(const void* p) {
    unsigned int a;
    asm("{ .reg .u64 t; cvta.to.shared.u64 t, %1; cvt.u32.u64 %0, t; }"
        : "=r"(a) : "l"(p));
    return a;
}

__device__ __forceinline__ void cluster_arrive_wait() {
    asm volatile("barrier.cluster.arrive.aligned;" ::: "memory");
    asm volatile("barrier.cluster.wait.aligned;" ::: "memory");
}

__device__ __forceinline__ void mbar_wait_parity(unsigned int mb,
                                                 unsigned int parity) {
    asm volatile(
        "{\n\t"
        ".reg .pred P;\n\t"
        "WL%=:\n\t"
        "mbarrier.try_wait.parity.acquire.cta.shared::cta.b64 P, [%0], %1, 0x989680;\n\t"
        "@!P bra WL%=;\n\t"
        "}"
        :: "r"(mb), "r"(parity) : "memory");
}

__global__ void __cluster_dims__(RB, 1, 1) __launch_bounds__(RT, 1)
rnn_kernel(const float* __restrict__ gi,
           const float* __restrict__ Whh,
           const float* __restrict__ bhh,
           float* __restrict__ out,
           int out_size) {
    __shared__ __align__(16) float hbuf[2][H];
    __shared__ __align__(8) unsigned long long mbar_g[2][4];  // [parity][group]
    __shared__ __align__(8) unsigned long long mbar_f[2];     // final join

    int blk = blockIdx.x;
    int tid = threadIdx.x;
    int w = tid >> 5;                 // warp 0..7
    int lane = tid & 31;
    int grp = w & 3;

    // weights: rows (g, dd) -> global row g*256 + blk*32 + w*4 + dd (12 rows),
    // cols lane*8..lane*8+7 packed f32x2: 12 x 4 ull = 48 ull
    unsigned long long w2[12][4];
#pragma unroll
    for (int g = 0; g < 3; g++) {
#pragma unroll
        for (int dd = 0; dd < 4; dd++) {
            int rowg = g * 256 + blk * 32 + w * 4 + dd;
            const unsigned long long* src =
                (const unsigned long long*)(Whh + (size_t)rowg * H + lane * 8);
#pragma unroll
            for (int i = 0; i < 4; i++) w2[g * 4 + dd][i] = src[i];
        }
    }

    for (int i = tid; i < 2 * H; i += RT) ((float*)hbuf)[i] = 0.f;

    unsigned int lg[2][4];
#pragma unroll
    for (int pp = 0; pp < 2; pp++)
#pragma unroll
        for (int gg = 0; gg < 4; gg++)
            lg[pp][gg] = smem_u32(&mbar_g[pp][gg]);
    unsigned int lf0 = smem_u32(&mbar_f[0]);
    unsigned int lf1 = smem_u32(&mbar_f[1]);

    if (tid < 4) {
#pragma unroll
        for (int pp = 0; pp < 2; pp++) {
            asm volatile("mbarrier.init.shared.b64 [%0], %1;"
                         :: "r"(lg[pp][tid]), "r"(1) : "memory");
            // pre-arm: 2 warps x 8 CTAs x 16B = 256B per phase
            asm volatile("mbarrier.arrive.expect_tx.shared.b64 _, [%0], %1;"
                         :: "r"(lg[pp][tid]), "r"(256) : "memory");
        }
    }
    if (tid == 0) {
        asm volatile("mbarrier.init.shared.b64 [%0], %1;"
                     :: "r"(lf0), "r"(4) : "memory");
        asm volatile("mbarrier.init.shared.b64 [%0], %1;"
                     :: "r"(lf1), "r"(4) : "memory");
    }

    // owner lanes 0..3 of each warp own dim d = w*4 + lane
    int d = w * 4 + lane;             // meaningful for lane < 4
    int j = blk * 32 + d;
    int jc = j & 255;
    bool owner = (lane < 4);
    float ir = 0.f, iz = 0.f, inn = 0.f, bh_r = 0.f, bh_z = 0.f, bh_n = 0.f;
    if (owner) {
        ir = gi[j];
        iz = gi[256 + j];
        inn = gi[512 + j];
        bh_r = bhh[j];
        bh_z = bhh[256 + j];
        bh_n = bhh[512 + j];
    }
    unsigned int hb0 = smem_u32(&hbuf[0][lane * 8]);
    unsigned int hb1 = smem_u32(&hbuf[1][lane * 8]);

    // remote addresses: warp slot (16B) + this warp's GROUP mbar on each CTA
    unsigned int wl0 = smem_u32(&hbuf[0][blk * 32 + w * 4]);
    unsigned int wl1 = smem_u32(&hbuf[1][blk * 32 + w * 4]);
    int rr = lane & 7;
    unsigned int pdst0, pdst1, pmb0, pmb1;
    asm("mapa.shared::cluster.u32 %0, %1, %2;" : "=r"(pdst0) : "r"(wl0), "r"(rr));
    asm("mapa.shared::cluster.u32 %0, %1, %2;" : "=r"(pdst1) : "r"(wl1), "r"(rr));
    asm("mapa.shared::cluster.u32 %0, %1, %2;" : "=r"(pmb0) : "r"(lg[0][grp]), "r"(rr));
    asm("mapa.shared::cluster.u32 %0, %1, %2;" : "=r"(pmb1) : "r"(lg[1][grp]), "r"(rr));

    __syncthreads();
    cluster_arrive_wait();

    for (int t = 0; t < S; t++) {
        int p = t & 1;

        // ---- dot: 12 rows x 8 cols per thread (f32x2) ----
        unsigned int haddr = p ? hb1 : hb0;
        unsigned long long h2[4];
        asm volatile("ld.shared.v2.b64 {%0, %1}, [%4];\n\t"
                     "ld.shared.v2.b64 {%2, %3}, [%4 + 16];"
                     : "=l"(h2[0]), "=l"(h2[1]), "=l"(h2[2]), "=l"(h2[3])
                     : "r"(haddr));
        float a[12];
#pragma unroll
        for (int r = 0; r < 12; r++) {
            unsigned long long acc2 = 0ull;
#pragma unroll
            for (int i = 0; i < 4; i++) {
                asm("fma.rn.f32x2 %0, %1, %2, %0;"
                    : "+l"(acc2) : "l"(w2[r][i]), "l"(h2[i]));
            }
            float lo, hi;
            asm("mov.b64 {%0, %1}, %2;" : "=f"(lo), "=f"(hi) : "l"(acc2));
            a[r] = lo + hi;
        }

        // ---- two-level role-fold butterfly: 12 -> 6 -> 3 arrays ----
        int l0 = lane & 1;
        int l1 = (lane >> 1) & 1;
        float b6[6];
#pragma unroll
        for (int g = 0; g < 3; g++) {
#pragma unroll
            for (int d1 = 0; d1 < 2; d1++) {
                float x = a[g * 4 + (d1 << 1) + 0];
                float y = a[g * 4 + (d1 << 1) + 1];
                float keep = l0 ? y : x;
                float send = l0 ? x : y;
                b6[g * 2 + d1] = keep + __shfl_xor_sync(0xffffffffu, send, 1);
            }
        }
        float z3[3];
#pragma unroll
        for (int g = 0; g < 3; g++) {
            float x = b6[g * 2 + 0];
            float y = b6[g * 2 + 1];
            float keep = l1 ? y : x;
            float send = l1 ? x : y;
            z3[g] = keep + __shfl_xor_sync(0xffffffffu, send, 2);
        }
#pragma unroll
        for (int m = 4; m <= 16; m <<= 1) {
#pragma unroll
            for (int g = 0; g < 3; g++)
                z3[g] += __shfl_xor_sync(0xffffffffu, z3[g], m);
        }

        // ---- gate math (all lanes SIMT; lanes 0..3 meaningful) ----
        float ghr = z3[0] + bh_r;
        float ghz = z3[1] + bh_z;
        float ghn = z3[2] + bh_n;
        float hold = hbuf[p][jc];
        float r = 1.f / (1.f + __expf(-(ir + ghr)));
        float z = 1.f / (1.f + __expf(-(iz + ghz)));
        float narg = inn + r * ghn;
        float n = 1.f - 2.f / (1.f + __expf(2.f * narg));
        float hnew = (1.f - z) * n + z * hold;

        float b0 = __shfl_sync(0xffffffffu, hnew, 0);
        float b1 = __shfl_sync(0xffffffffu, hnew, 1);
        float b2 = __shfl_sync(0xffffffffu, hnew, 2);
        float b3 = __shfl_sync(0xffffffffu, hnew, 3);

        // ---- st.async exchange: lanes 0..7, one 16B packet each ----
        if (lane < 8) {
            unsigned int pd = p ? pdst0 : pdst1;   // write hbuf[p^1]
            unsigned int pm = p ? pmb1 : pmb0;     // count on group mbar[p]
            asm volatile(
                "st.async.shared::cluster.mbarrier::complete_tx::bytes.v4.b32 "
                "[%0], {%1, %2, %3, %4}, [%5];"
                :: "r"(pd), "f"(b0), "f"(b1), "f"(b2), "f"(b3), "r"(pm)
                : "memory");
        }

        // prefetch next token's gi (hidden by the wait)
        if (owner) {
            int tn = (t + 1 < S) ? (t + 1) : t;
            ir = gi[(size_t)tn * G3 + j];
            iz = gi[(size_t)tn * G3 + 256 + j];
            inn = gi[(size_t)tn * G3 + 512 + j];
        }

        // ---- collector-tree join ----
        unsigned int parity = (unsigned int)((t >> 1) & 1);
        unsigned int lfp = p ? lf1 : lf0;
        if (lane == 0) {
            if (w < 4) {
                // collector: wait own group's mbar, re-arm it, arrive final
                mbar_wait_parity(lg[p][w], parity);
                asm volatile("mbarrier.arrive.expect_tx.shared.b64 _, [%0], %1;"
                             :: "r"(lg[p][w]), "r"(256) : "memory");
                asm volatile("mbarrier.arrive.shared.b64 _, [%0];"
                             :: "r"(lfp) : "memory");
            }
            mbar_wait_parity(lfp, parity);
        }
        __syncwarp();
    }

    if (blk == 0) {
        for (int i = tid; i < out_size; i += RT)
            out[i] = hbuf[0][i & 255];
    }
}

// ---------------- host launcher ----------------
extern "C" void kernel_launch(void* const* d_in, const int* in_sizes, int n_in,
                              void* d_out, int out_size) {
    const int* tokens = (const int*)d_in[0];
    const float* emb = (const float*)d_in[1];
    const float* Wq = (const float*)d_in[2];
    const float* bq = (const float*)d_in[3];
    const float* Wk = (const float*)d_in[4];
    const float* bk = (const float*)d_in[5];
    const float* Wv = (const float*)d_in[6];
    const float* bv = (const float*)d_in[7];
    const float* Wo = (const float*)d_in[8];
    const float* bo = (const float*)d_in[9];
    const float* ln_g = (const float*)d_in[10];
    const float* ln_b = (const float*)d_in[11];
    const float* W_ih = (const float*)d_in[12];
    const float* W_hh = (const float*)d_in[13];
    const float* b_ih = (const float*)d_in[14];
    const float* b_hh = (const float*)d_in[15];
    float* out = (float*)d_out;

    float* px; cudaGetSymbolAddress((void**)&px, g_x);
    float* pq; cudaGetSymbolAddress((void**)&pq, g_q);
    float* pk; cudaGetSymbolAddress((void**)&pk, g_k);
    float* pv; cudaGetSymbolAddress((void**)&pv, g_v);
    float* po; cudaGetSymbolAddress((void**)&po, g_o);
    float* pypre; cudaGetSymbolAddress((void**)&pypre, g_ypre);
    float* py; cudaGetSymbolAddress((void**)&py, g_y);
    float* pgi; cudaGetSymbolAddress((void**)&pgi, g_gi);

    size_t attn_smem = (size_t)(3 * 64 * LDQ + 64 * LDP + 64) * sizeof(float);
    cudaFuncSetAttribute(attn_kernel, cudaFuncAttributeMaxDynamicSharedMemorySize,
                         (int)attn_smem);

    embed_kernel<<<S, 64>>>(tokens, emb);

    dim3 gqkv(4, 64, 3 * NH);
    gemm_qkv<<<gqkv, 256>>>(px, Wq, bq, Wk, bk, Wv, bv, pq, pk, pv);

    dim3 gatt(S / 64, NH);
    attn_kernel<<<gatt, 256, attn_smem>>>(pq, pk, pv, po);

    dim3 gop(4, 64, 1);
    gemm_op<<<gop, 256>>>(po, Wo, bo, px, pypre);

    ln_kernel<<<S / 8, 256>>>(pypre, ln_g, ln_b, py);

    dim3 ggi(12, 64, 1);
    gemm_gi<<<ggi, 256>>>(py, W_ih, b_ih, pgi);

    rnn_kernel<<<RB, RT>>>(pgi, W_hh, b_hh, out, out_size);
}

// round 16
// speedup vs baseline: 1.0661x; 1.0661x over previous
#include <cuda_runtime.h>
#include <cuda_bf16.h>
#include <mma.h>
#include <math.h>
#include <stddef.h>

using namespace nvcuda;

#define S 4096
#define H 256
#define NH 6
#define G3 768
#define EPS 1e-5f

// ---------------- scratch (static device arrays; no allocation) ----------------
__device__ float g_x[S * H];
__device__ float g_q[NH * S * H];
__device__ float g_k[NH * S * H];
__device__ float g_v[NH * S * H];
__device__ float g_o[NH * S * H];
__device__ float g_ypre[S * H];
__device__ float g_y[S * H];
__device__ float g_gi[S * G3];

// ---------------- embedding gather ----------------
__global__ void embed_kernel(const int* __restrict__ tokens,
                             const float* __restrict__ emb) {
    int s = blockIdx.x;
    int tok = tokens[s];
    const float4* src = (const float4*)(emb + (size_t)tok * H);
    float4* dst = (float4*)(g_x + (size_t)s * H);
    dst[threadIdx.x] = src[threadIdx.x];
}

// ---------------- WMMA tf32 QKV GEMM, all 3 projections in one launch --------
#define LDG_ 68
__global__ __launch_bounds__(256) void gemm_qkv(const float* __restrict__ A,
                                                const float* __restrict__ Wq,
                                                const float* __restrict__ bq,
                                                const float* __restrict__ Wk,
                                                const float* __restrict__ bk,
                                                const float* __restrict__ Wv,
                                                const float* __restrict__ bv,
                                                float* __restrict__ Cq,
                                                float* __restrict__ Ck,
                                                float* __restrict__ Cv) {
    __shared__ float As[64 * LDG_];
    __shared__ float Bs[64 * LDG_];
    int tid = threadIdx.x;
    int warp = tid >> 5;
    int wm = warp & 3;
    int wn = warp >> 2;
    int m0 = blockIdx.y * 64, n0 = blockIdx.x * 64;
    int z = blockIdx.z;
    int which = z / 6, zh = z - which * 6;
    const float* Bb = ((which == 0) ? Wq : (which == 1) ? Wk : Wv) +
                      (size_t)zh * 256 * 256;
    const float* bias = ((which == 0) ? bq : (which == 1) ? bk : bv) + zh * 256;
    float* C = ((which == 0) ? Cq : (which == 1) ? Ck : Cv);

    wmma::fragment<wmma::accumulator, 16, 16, 8, float> c[2];
    wmma::fill_fragment(c[0], 0.0f);
    wmma::fill_fragment(c[1], 0.0f);

    for (int k0 = 0; k0 < 256; k0 += 64) {
        const float* Asrc = A + k0;
        for (int i = tid; i < 64 * 16; i += 256) {
            int m = i >> 4, k4 = i & 15;
            float4 v = *(const float4*)(Asrc + (size_t)(m0 + m) * 256 + k4 * 4);
            *(float4*)(As + m * LDG_ + k4 * 4) = v;
        }
        for (int i = tid; i < 64 * 16; i += 256) {
            int kk = i >> 4, n4 = i & 15;
            float4 v = *(const float4*)(Bb + (size_t)(k0 + kk) * 256 + n0 + n4 * 4);
            *(float4*)(Bs + kk * LDG_ + n4 * 4) = v;
        }
        __syncthreads();

        wmma::fragment<wmma::matrix_a, 16, 16, 8, wmma::precision::tf32,
                       wmma::row_major> af;
        wmma::fragment<wmma::matrix_b, 16, 16, 8, wmma::precision::tf32,
                       wmma::row_major> bf;
#pragma unroll
        for (int k = 0; k < 8; k++) {
            wmma::load_matrix_sync(af, As + (wm * 16) * LDG_ + k * 8, LDG_);
#pragma unroll
            for (int e = 0; e < af.num_elements; e++)
                af.x[e] = wmma::__float_to_tf32(af.x[e]);
#pragma unroll
            for (int nf = 0; nf < 2; nf++) {
                wmma::load_matrix_sync(
                    bf, Bs + (k * 8) * LDG_ + wn * 32 + nf * 16, LDG_);
#pragma unroll
                for (int e = 0; e < bf.num_elements; e++)
                    bf.x[e] = wmma::__float_to_tf32(bf.x[e]);
                wmma::mma_sync(c[nf], af, bf, c[nf]);
            }
        }
        __syncthreads();
    }

#pragma unroll
    for (int nf = 0; nf < 2; nf++)
        wmma::store_matrix_sync(As + (wm * 16) * LDG_ + wn * 32 + nf * 16,
                                c[nf], LDG_, wmma::mem_row_major);
    __syncthreads();

    for (int i = tid; i < 64 * 64; i += 256) {
        int m = i >> 6, n = i & 63;
        int gm = m0 + m, gn = n0 + n;
        float v = As[m * LDG_ + n] + bias[gn];
        C[(size_t)zh * S * 256 + (size_t)gm * 256 + gn] = v;
    }
}

// ---------------- WMMA tf32 out-proj (+residual) -----------------------------
__global__ __launch_bounds__(256) void gemm_op(const float* __restrict__ A,
                                               const float* __restrict__ B,
                                               const float* __restrict__ bias,
                                               const float* __restrict__ resid,
                                               float* __restrict__ C) {
    __shared__ float As[64 * LDG_];
    __shared__ float Bs[64 * LDG_];
    int tid = threadIdx.x;
    int warp = tid >> 5;
    int wm = warp & 3;
    int wn = warp >> 2;
    int m0 = blockIdx.y * 64, n0 = blockIdx.x * 64;

    wmma::fragment<wmma::accumulator, 16, 16, 8, float> c[2];
    wmma::fill_fragment(c[0], 0.0f);
    wmma::fill_fragment(c[1], 0.0f);

    for (int k0 = 0; k0 < 1536; k0 += 64) {
        const float* Asrc = A + (size_t)(k0 >> 8) * (S * 256) + (k0 & 255);
        for (int i = tid; i < 64 * 16; i += 256) {
            int m = i >> 4, k4 = i & 15;
            float4 v = *(const float4*)(Asrc + (size_t)(m0 + m) * 256 + k4 * 4);
            *(float4*)(As + m * LDG_ + k4 * 4) = v;
        }
        for (int i = tid; i < 64 * 16; i += 256) {
            int kk = i >> 4, n4 = i & 15;
            float4 v = *(const float4*)(B + (size_t)(k0 + kk) * 256 + n0 + n4 * 4);
            *(float4*)(Bs + kk * LDG_ + n4 * 4) = v;
        }
        __syncthreads();

        wmma::fragment<wmma::matrix_a, 16, 16, 8, wmma::precision::tf32,
                       wmma::row_major> af;
        wmma::fragment<wmma::matrix_b, 16, 16, 8, wmma::precision::tf32,
                       wmma::row_major> bf;
#pragma unroll
        for (int k = 0; k < 8; k++) {
            wmma::load_matrix_sync(af, As + (wm * 16) * LDG_ + k * 8, LDG_);
#pragma unroll
            for (int e = 0; e < af.num_elements; e++)
                af.x[e] = wmma::__float_to_tf32(af.x[e]);
#pragma unroll
            for (int nf = 0; nf < 2; nf++) {
                wmma::load_matrix_sync(
                    bf, Bs + (k * 8) * LDG_ + wn * 32 + nf * 16, LDG_);
#pragma unroll
                for (int e = 0; e < bf.num_elements; e++)
                    bf.x[e] = wmma::__float_to_tf32(bf.x[e]);
                wmma::mma_sync(c[nf], af, bf, c[nf]);
            }
        }
        __syncthreads();
    }

#pragma unroll
    for (int nf = 0; nf < 2; nf++)
        wmma::store_matrix_sync(As + (wm * 16) * LDG_ + wn * 32 + nf * 16,
                                c[nf], LDG_, wmma::mem_row_major);
    __syncthreads();

    for (int i = tid; i < 64 * 64; i += 256) {
        int m = i >> 6, n = i & 63;
        int gm = m0 + m, gn = n0 + n;
        float v = As[m * LDG_ + n] + bias[gn] + resid[(size_t)gm * 256 + gn];
        C[(size_t)gm * 256 + gn] = v;
    }
}

// ---------------- fp32 SIMT GEMM for gi = y @ W_ih^T + b_ih ------------------
__global__ __launch_bounds__(256) void gemm_gi(const float* __restrict__ A,
                                               const float* __restrict__ B,
                                               const float* __restrict__ bias,
                                               float* __restrict__ C) {
    __shared__ float As[64][65];
    __shared__ float Bs[64][65];
    int tid = threadIdx.x;
    int m0 = blockIdx.y * 64, n0 = blockIdx.x * 64;

    float acc[4][4];
#pragma unroll
    for (int i = 0; i < 4; i++)
#pragma unroll
        for (int j = 0; j < 4; j++) acc[i][j] = 0.f;

    int ty = tid >> 4, tx = tid & 15;

    for (int k0 = 0; k0 < 256; k0 += 64) {
#pragma unroll
        for (int i = 0; i < 16; i++) {
            int lin = i * 256 + tid;
            int m = lin >> 6, kk = lin & 63;
            As[m][kk] = A[(size_t)(m0 + m) * 256 + k0 + kk];
        }
#pragma unroll
        for (int i = 0; i < 16; i++) {
            int lin = i * 256 + tid;
            int n = lin >> 6, kk = lin & 63;
            Bs[kk][n] = B[(size_t)(n0 + n) * 256 + (k0 + kk)];
        }
        __syncthreads();
#pragma unroll 8
        for (int kk = 0; kk < 64; kk++) {
            float a[4], b[4];
#pragma unroll
            for (int i = 0; i < 4; i++) a[i] = As[ty * 4 + i][kk];
#pragma unroll
            for (int j = 0; j < 4; j++) b[j] = Bs[kk][tx * 4 + j];
#pragma unroll
            for (int i = 0; i < 4; i++)
#pragma unroll
                for (int j = 0; j < 4; j++) acc[i][j] += a[i] * b[j];
        }
        __syncthreads();
    }

#pragma unroll
    for (int i = 0; i < 4; i++) {
        int m = m0 + ty * 4 + i;
#pragma unroll
        for (int j = 0; j < 4; j++) {
            int n = n0 + tx * 4 + j;
            C[(size_t)m * 768 + n] = acc[i][j] + bias[n];
        }
    }
}

// ---------------- WMMA tf32 attention with cp.async pipelining ---------------
// Single K/V smem buffers, but loads are cp.async: V(t) issued at loop top
// (consumed only at PV, hidden behind QK+exp), K(t+1) issued right after the
// post-QK barrier (hidden behind exp+PV+next loop top). Commit groups:
// outstanding at PV-wait = {V(t), K(t+1)} -> wait_group 1; at top = {K(t)}
// -> wait_group 0.
#define LDQ 268
#define LDP 76

__device__ __forceinline__ unsigned int smem_u32a(const void* p) {
    unsigned int a;
    asm("{ .reg .u64 t; cvta.to.shared.u64 t, %1; cvt.u32.u64 %0, t; }"
        : "=r"(a) : "l"(p));
    return a;
}

__device__ __forceinline__ void cp_async16(unsigned int saddr, const void* g) {
    asm volatile("cp.async.cg.shared.global [%0], [%1], 16;"
                 :: "r"(saddr), "l"(g));
}

__global__ __launch_bounds__(256) void attn_kernel(const float* __restrict__ Q,
                                                   const float* __restrict__ K,
                                                   const float* __restrict__ V,
                                                   float* __restrict__ O) {
    extern __shared__ float sm[];
    float* Qs = sm;
    float* Ks = Qs + 64 * LDQ;
    float* Vs = Ks + 64 * LDQ;
    float* Ps = Vs + 64 * LDQ;
    float* Ls = Ps + 64 * LDP;

    int h = blockIdx.y;
    int q0 = blockIdx.x * 64;
    int tid = threadIdx.x;
    int warp = tid >> 5;
    int wm = warp & 3;
    int wn = warp >> 2;

    const float* Qg = Q + ((size_t)h * S + q0) * H;
    const float* Kg = K + (size_t)h * S * H;
    const float* Vg = V + (size_t)h * S * H;

    unsigned int ks_base = smem_u32a(Ks);
    unsigned int vs_base = smem_u32a(Vs);

    // issue K(0) first (deepest latency cover), then stage Q
    for (int i = tid; i < 64 * 64; i += 256) {
        int r = i >> 6, d4 = i & 63;
        cp_async16(ks_base + (unsigned)(r * LDQ + d4 * 4) * 4,
                   Kg + (size_t)r * H + d4 * 4);
    }
    asm volatile("cp.async.commit_group;" ::: "memory");

    for (int i = tid; i < 64 * 64; i += 256) {
        int q = i >> 6, d4 = i & 63;
        ((float4*)(Qs + q * LDQ))[d4] = ((const float4*)(Qg + (size_t)q * H))[d4];
    }

    wmma::fragment<wmma::accumulator, 16, 16, 8, float> o_frag[8];
#pragma unroll
    for (int f = 0; f < 8; f++) wmma::fill_fragment(o_frag[f], 0.0f);

    int lrow = tid >> 2;
    int lcol0 = (tid & 3) * 16;
    float l_part = 0.f;
    const float inv_scale = 0.0625f;

    for (int kt = 0; kt < S / 64; kt++) {
        // K(t) ready; PV(t-1) finished (barrier)
        asm volatile("cp.async.wait_group 0;" ::: "memory");
        __syncthreads();

        // issue V(t) -> Vs (free since PV(t-1) done); consumed at PV(t)
        for (int i = tid; i < 64 * 64; i += 256) {
            int r = i >> 6, d4 = i & 63;
            cp_async16(vs_base + (unsigned)(r * LDQ + d4 * 4) * 4,
                       Vg + (size_t)(kt * 64 + r) * H + d4 * 4);
        }
        asm volatile("cp.async.commit_group;" ::: "memory");

        // ---- QK(t): S = Q @ K^T ----
        {
            wmma::fragment<wmma::matrix_a, 16, 16, 8, wmma::precision::tf32,
                           wmma::row_major> af;
            wmma::fragment<wmma::matrix_b, 16, 16, 8, wmma::precision::tf32,
                           wmma::col_major> bf;
            wmma::fragment<wmma::accumulator, 16, 16, 8, float> c[2];
            wmma::fill_fragment(c[0], 0.0f);
            wmma::fill_fragment(c[1], 0.0f);
#pragma unroll 4
            for (int k = 0; k < 32; k++) {
                wmma::load_matrix_sync(af, Qs + (wm * 16) * LDQ + k * 8, LDQ);
#pragma unroll
                for (int e = 0; e < af.num_elements; e++)
                    af.x[e] = wmma::__float_to_tf32(af.x[e]);
#pragma unroll
                for (int nf = 0; nf < 2; nf++) {
                    wmma::load_matrix_sync(
                        bf, Ks + (wn * 32 + nf * 16) * LDQ + k * 8, LDQ);
#pragma unroll
                    for (int e = 0; e < bf.num_elements; e++)
                        bf.x[e] = wmma::__float_to_tf32(bf.x[e]);
                    wmma::mma_sync(c[nf], af, bf, c[nf]);
                }
            }
#pragma unroll
            for (int nf = 0; nf < 2; nf++)
                wmma::store_matrix_sync(
                    Ps + (wm * 16) * LDP + wn * 32 + nf * 16, c[nf], LDP,
                    wmma::mem_row_major);
        }
        __syncthreads();   // QK done (Ks free), Ps visible

        // issue K(t+1) -> Ks; consumed at next loop top
        {
            int ktn = (kt + 1 < S / 64) ? (kt + 1) : kt;
            for (int i = tid; i < 64 * 64; i += 256) {
                int r = i >> 6, d4 = i & 63;
                cp_async16(ks_base + (unsigned)(r * LDQ + d4 * 4) * 4,
                           Kg + (size_t)(ktn * 64 + r) * H + d4 * 4);
            }
            asm volatile("cp.async.commit_group;" ::: "memory");
        }

        // ---- exp in place + row-sum partials ----
        {
            float* pr = Ps + lrow * LDP + lcol0;
            float ssum = 0.f;
#pragma unroll
            for (int j = 0; j < 16; j++) {
                float e = __expf(pr[j] * inv_scale);
                pr[j] = e;
                ssum += e;
            }
            l_part += ssum;
        }

        // V(t) complete (leave K(t+1) in flight); exp results visible
        asm volatile("cp.async.wait_group 1;" ::: "memory");
        __syncthreads();

        // ---- PV(t): O += P @ V ----
        {
            wmma::fragment<wmma::matrix_a, 16, 16, 8, wmma::precision::tf32,
                           wmma::row_major> pa;
            wmma::fragment<wmma::matrix_b, 16, 16, 8, wmma::precision::tf32,
                           wmma::row_major> vb;
#pragma unroll
            for (int k = 0; k < 8; k++) {
                wmma::load_matrix_sync(pa, Ps + (wm * 16) * LDP + k * 8, LDP);
#pragma unroll
                for (int e = 0; e < pa.num_elements; e++)
                    pa.x[e] = wmma::__float_to_tf32(pa.x[e]);
#pragma unroll
                for (int nf = 0; nf < 8; nf++) {
                    wmma::load_matrix_sync(
                        vb, Vs + (k * 8) * LDQ + wn * 128 + nf * 16, LDQ);
#pragma unroll
                    for (int e = 0; e < vb.num_elements; e++)
                        vb.x[e] = wmma::__float_to_tf32(vb.x[e]);
                    wmma::mma_sync(o_frag[nf], pa, vb, o_frag[nf]);
                }
            }
        }
    }

    l_part += __shfl_xor_sync(0xffffffffu, l_part, 1);
    l_part += __shfl_xor_sync(0xffffffffu, l_part, 2);
    if ((tid & 3) == 0) Ls[lrow] = l_part;

#pragma unroll
    for (int nf = 0; nf < 8; nf++)
        wmma::store_matrix_sync(Qs + (wm * 16) * LDQ + wn * 128 + nf * 16,
                                o_frag[nf], LDQ, wmma::mem_row_major);
    __syncthreads();

    float* Og = O + ((size_t)h * S + q0) * H;
    for (int i = tid; i < 64 * 64; i += 256) {
        int q = i >> 6, d4 = i & 63;
        float inv_l = __frcp_rn(Ls[q]);
        float4 v = ((float4*)(Qs + q * LDQ))[d4];
        v.x *= inv_l; v.y *= inv_l; v.z *= inv_l; v.w *= inv_l;
        ((float4*)(Og + (size_t)q * H))[d4] = v;
    }
}

// ---------------- LayerNorm (one warp per row) ----------------
__global__ __launch_bounds__(256) void ln_kernel(const float* __restrict__ yin,
                                                 const float* __restrict__ g,
                                                 const float* __restrict__ b,
                                                 float* __restrict__ yout) {
    int row = blockIdx.x * 8 + (threadIdx.x >> 5);
    int lane = threadIdx.x & 31;
    const float* yr = yin + (size_t)row * H;
    float v[8], s = 0.f, sq = 0.f;
#pragma unroll
    for (int i = 0; i < 8; i++) {
        v[i] = yr[lane + i * 32];
        s += v[i];
        sq += v[i] * v[i];
    }
#pragma unroll
    for (int m = 16; m >= 1; m >>= 1) {
        s += __shfl_xor_sync(0xffffffffu, s, m);
        sq += __shfl_xor_sync(0xffffffffu, sq, m);
    }
    float mu = s * (1.f / H);
    float var = sq * (1.f / H) - mu * mu;
    float rstd = rsqrtf(var + EPS);
    float* yo = yout + (size_t)row * H;
#pragma unroll
    for (int i = 0; i < 8; i++) {
        int c = lane + i * 32;
        yo[c] = (v[i] - mu) * rstd * g[c] + b[c];
    }
}

// ---------------- GRU recurrence: 8-CTA cluster, 16B-packet st.async ---------
// Byte-identical to R14 (best RNN so far): 8 warps/CTA, 4 dims/warp, one
// 16B st.async packet per (warp, target CTA), single mbar per parity,
// lane0 waiter, off-path re-arm by tid0.
#define RB 8
#define RT 256

__device__ __forceinline__ unsigned int smem_u32(const void* p) {
    unsigned int a;
    asm("{ .reg .u64 t; cvta.to.shared.u64 t, %1; cvt.u32.u64 %0, t; }"
        : "=r"(a) : "l"(p));
    return a;
}

__device__ __forceinline__ void cluster_arrive_wait() {
    asm volatile("barrier.cluster.arrive.aligned;" ::: "memory");
    asm volatile("barrier.cluster.wait.aligned;" ::: "memory");
}

__device__ __forceinline__ void mbar_wait_parity(unsigned int mb,
                                                 unsigned int parity) {
    asm volatile(
        "{\n\t"
        ".reg .pred P;\n\t"
        "WL%=:\n\t"
        "mbarrier.try_wait.parity.acquire.cta.shared::cta.b64 P, [%0], %1, 0x989680;\n\t"
        "@!P bra WL%=;\n\t"
        "}"
        :: "r"(mb), "r"(parity) : "memory");
}

__global__ void __cluster_dims__(RB, 1, 1) __launch_bounds__(RT, 1)
rnn_kernel(const float* __restrict__ gi,
           const float* __restrict__ Whh,
           const float* __restrict__ bhh,
           float* __restrict__ out,
           int out_size) {
    __shared__ __align__(16) float hbuf[2][H];
    __shared__ __align__(8) unsigned long long mbar[2];

    int blk = blockIdx.x;
    int tid = threadIdx.x;
    int w = tid >> 5;                 // warp 0..7
    int lane = tid & 31;

    unsigned long long w2[12][4];
#pragma unroll
    for (int g = 0; g < 3; g++) {
#pragma unroll
        for (int dd = 0; dd < 4; dd++) {
            int rowg = g * 256 + blk * 32 + w * 4 + dd;
            const unsigned long long* src =
                (const unsigned long long*)(Whh + (size_t)rowg * H + lane * 8);
#pragma unroll
            for (int i = 0; i < 4; i++) w2[g * 4 + dd][i] = src[i];
        }
    }

    for (int i = tid; i < 2 * H; i += RT) ((float*)hbuf)[i] = 0.f;

    unsigned int mb0 = smem_u32(&mbar[0]);
    unsigned int mb1 = smem_u32(&mbar[1]);
    if (tid == 0) {
        asm volatile("mbarrier.init.shared.b64 [%0], %1;"
                     :: "r"(mb0), "r"(1) : "memory");
        asm volatile("mbarrier.init.shared.b64 [%0], %1;"
                     :: "r"(mb1), "r"(1) : "memory");
        asm volatile("mbarrier.arrive.expect_tx.shared.b64 _, [%0], %1;"
                     :: "r"(mb0), "r"(1024) : "memory");
        asm volatile("mbarrier.arrive.expect_tx.shared.b64 _, [%0], %1;"
                     :: "r"(mb1), "r"(1024) : "memory");
    }

    int d = w * 4 + lane;             // meaningful for lane < 4
    int j = blk * 32 + d;
    int jc = j & 255;
    bool owner = (lane < 4);
    float ir = 0.f, iz = 0.f, inn = 0.f, bh_r = 0.f, bh_z = 0.f, bh_n = 0.f;
    if (owner) {
        ir = gi[j];
        iz = gi[256 + j];
        inn = gi[512 + j];
        bh_r = bhh[j];
        bh_z = bhh[256 + j];
        bh_n = bhh[512 + j];
    }
    unsigned int hb0 = smem_u32(&hbuf[0][lane * 8]);
    unsigned int hb1 = smem_u32(&hbuf[1][lane * 8]);

    unsigned int wl0 = smem_u32(&hbuf[0][blk * 32 + w * 4]);
    unsigned int wl1 = smem_u32(&hbuf[1][blk * 32 + w * 4]);
    int rr = lane & 7;
    unsigned int pdst0, pdst1, pmb0, pmb1;
    asm("mapa.shared::cluster.u32 %0, %1, %2;" : "=r"(pdst0) : "r"(wl0), "r"(rr));
    asm("mapa.shared::cluster.u32 %0, %1, %2;" : "=r"(pdst1) : "r"(wl1), "r"(rr));
    asm("mapa.shared::cluster.u32 %0, %1, %2;" : "=r"(pmb0) : "r"(mb0), "r"(rr));
    asm("mapa.shared::cluster.u32 %0, %1, %2;" : "=r"(pmb1) : "r"(mb1), "r"(rr));

    __syncthreads();
    cluster_arrive_wait();

    for (int t = 0; t < S; t++) {
        int p = t & 1;

        unsigned int haddr = p ? hb1 : hb0;
        unsigned long long h2[4];
        asm volatile("ld.shared.v2.b64 {%0, %1}, [%4];\n\t"
                     "ld.shared.v2.b64 {%2, %3}, [%4 + 16];"
                     : "=l"(h2[0]), "=l"(h2[1]), "=l"(h2[2]), "=l"(h2[3])
                     : "r"(haddr));
        float a[12];
#pragma unroll
        for (int r = 0; r < 12; r++) {
            unsigned long long acc2 = 0ull;
#pragma unroll
            for (int i = 0; i < 4; i++) {
                asm("fma.rn.f32x2 %0, %1, %2, %0;"
                    : "+l"(acc2) : "l"(w2[r][i]), "l"(h2[i]));
            }
            float lo, hi;
            asm("mov.b64 {%0, %1}, %2;" : "=f"(lo), "=f"(hi) : "l"(acc2));
            a[r] = lo + hi;
        }

        int l0 = lane & 1;
        int l1 = (lane >> 1) & 1;
        float b6[6];
#pragma unroll
        for (int g = 0; g < 3; g++) {
#pragma unroll
            for (int d1 = 0; d1 < 2; d1++) {
                float x = a[g * 4 + (d1 << 1) + 0];
                float y = a[g * 4 + (d1 << 1) + 1];
                float keep = l0 ? y : x;
                float send = l0 ? x : y;
                b6[g * 2 + d1] = keep + __shfl_xor_sync(0xffffffffu, send, 1);
            }
        }
        float z3[3];
#pragma unroll
        for (int g = 0; g < 3; g++) {
            float x = b6[g * 2 + 0];
            float y = b6[g * 2 + 1];
            float keep = l1 ? y : x;
            float send = l1 ? x : y;
            z3[g] = keep + __shfl_xor_sync(0xffffffffu, send, 2);
        }
#pragma unroll
        for (int m = 4; m <= 16; m <<= 1) {
#pragma unroll
            for (int g = 0; g < 3; g++)
                z3[g] += __shfl_xor_sync(0xffffffffu, z3[g], m);
        }

        float ghr = z3[0] + bh_r;
        float ghz = z3[1] + bh_z;
        float ghn = z3[2] + bh_n;
        float hold = hbuf[p][jc];
        float r = 1.f / (1.f + __expf(-(ir + ghr)));
        float z = 1.f / (1.f + __expf(-(iz + ghz)));
        float narg = inn + r * ghn;
        float n = 1.f - 2.f / (1.f + __expf(2.f * narg));
        float hnew = (1.f - z) * n + z * hold;

        float b0 = __shfl_sync(0xffffffffu, hnew, 0);
        float b1 = __shfl_sync(0xffffffffu, hnew, 1);
        float b2 = __shfl_sync(0xffffffffu, hnew, 2);
        float b3 = __shfl_sync(0xffffffffu, hnew, 3);

        if (lane < 8) {
            unsigned int pd = p ? pdst0 : pdst1;
            unsigned int pm = p ? pmb1 : pmb0;
            asm volatile(
                "st.async.shared::cluster.mbarrier::complete_tx::bytes.v4.b32 "
                "[%0], {%1, %2, %3, %4}, [%5];"
                :: "r"(pd), "f"(b0), "f"(b1), "f"(b2), "f"(b3), "r"(pm)
                : "memory");
        }

        if (owner) {
            int tn = (t + 1 < S) ? (t + 1) : t;
            ir = gi[(size_t)tn * G3 + j];
            iz = gi[(size_t)tn * G3 + 256 + j];
            inn = gi[(size_t)tn * G3 + 512 + j];
        }

        unsigned int mbp = p ? mb1 : mb0;
        if (lane == 0) {
            mbar_wait_parity(mbp, (unsigned int)((t >> 1) & 1));
            if (tid == 0) {
                asm volatile("mbarrier.arrive.expect_tx.shared.b64 _, [%0], %1;"
                             :: "r"(mbp), "r"(1024) : "memory");
            }
        }
        __syncwarp();
    }

    if (blk == 0) {
        for (int i = tid; i < out_size; i += RT)
            out[i] = hbuf[0][i & 255];
    }
}

// ---------------- host launcher ----------------
extern "C" void kernel_launch(void* const* d_in, const int* in_sizes, int n_in,
                              void* d_out, int out_size) {
    const int* tokens = (const int*)d_in[0];
    const float* emb = (const float*)d_in[1];
    const float* Wq = (const float*)d_in[2];
    const float* bq = (const float*)d_in[3];
    const float* Wk = (const float*)d_in[4];
    const float* bk = (const float*)d_in[5];
    const float* Wv = (const float*)d_in[6];
    const float* bv = (const float*)d_in[7];
    const float* Wo = (const float*)d_in[8];
    const float* bo = (const float*)d_in[9];
    const float* ln_g = (const float*)d_in[10];
    const float* ln_b = (const float*)d_in[11];
    const float* W_ih = (const float*)d_in[12];
    const float* W_hh = (const float*)d_in[13];
    const float* b_ih = (const float*)d_in[14];
    const float* b_hh = (const float*)d_in[15];
    float* out = (float*)d_out;

    float* px; cudaGetSymbolAddress((void**)&px, g_x);
    float* pq; cudaGetSymbolAddress((void**)&pq, g_q);
    float* pk; cudaGetSymbolAddress((void**)&pk, g_k);
    float* pv; cudaGetSymbolAddress((void**)&pv, g_v);
    float* po; cudaGetSymbolAddress((void**)&po, g_o);
    float* pypre; cudaGetSymbolAddress((void**)&pypre, g_ypre);
    float* py; cudaGetSymbolAddress((void**)&py, g_y);
    float* pgi; cudaGetSymbolAddress((void**)&pgi, g_gi);

    size_t attn_smem = (size_t)(3 * 64 * LDQ + 64 * LDP + 64) * sizeof(float);
    cudaFuncSetAttribute(attn_kernel, cudaFuncAttributeMaxDynamicSharedMemorySize,
                         (int)attn_smem);

    embed_kernel<<<S, 64>>>(tokens, emb);

    dim3 gqkv(4, 64, 3 * NH);
    gemm_qkv<<<gqkv, 256>>>(px, Wq, bq, Wk, bk, Wv, bv, pq, pk, pv);

    dim3 gatt(S / 64, NH);
    attn_kernel<<<gatt, 256, attn_smem>>>(pq, pk, pv, po);

    dim3 gop(4, 64, 1);
    gemm_op<<<gop, 256>>>(po, Wo, bo, px, pypre);

    ln_kernel<<<S / 8, 256>>>(pypre, ln_g, ln_b, py);

    dim3 ggi(12, 64, 1);
    gemm_gi<<<ggi, 256>>>(py, W_ih, b_ih, pgi);

    rnn_kernel<<<RB, RT>>>(pgi, W_hh, b_hh, out, out_size);
}

// round 17
// speedup vs baseline: 1.0727x; 1.0062x over previous
#include <cuda_runtime.h>
#include <cuda_bf16.h>
#include <mma.h>
#include <math.h>
#include <stddef.h>

using namespace nvcuda;

#define S 4096
#define H 256
#define NH 6
#define G3 768
#define EPS 1e-5f

// ---------------- scratch (static device arrays; no allocation) ----------------
__device__ float g_x[S * H];
__device__ float g_q[NH * S * H];
__device__ float g_k[NH * S * H];
__device__ float g_v[NH * S * H];
__device__ float g_o[NH * S * H];
__device__ float g_ypre[S * H];
__device__ float g_y[S * H];
__device__ float g_gi[S * G3];

__device__ __forceinline__ unsigned int smem_u32g(const void* p) {
    unsigned int a;
    asm("{ .reg .u64 t; cvta.to.shared.u64 t, %1; cvt.u32.u64 %0, t; }"
        : "=r"(a) : "l"(p));
    return a;
}

__device__ __forceinline__ void cp_async16g(unsigned int saddr, const void* g) {
    asm volatile("cp.async.cg.shared.global [%0], [%1], 16;"
                 :: "r"(saddr), "l"(g));
}

// ---------------- embedding gather ----------------
__global__ void embed_kernel(const int* __restrict__ tokens,
                             const float* __restrict__ emb) {
    int s = blockIdx.x;
    int tok = tokens[s];
    const float4* src = (const float4*)(emb + (size_t)tok * H);
    float4* dst = (float4*)(g_x + (size_t)s * H);
    dst[threadIdx.x] = src[threadIdx.x];
}

// ---------------- WMMA tf32 GEMM with cp.async double buffering --------------
// QKV mode (KTOT=256, z selects proj+head) and out-proj mode (KTOT=1536,
// gathered A + residual) share the pipelined tile loop.
#define LDG_ 68
#define TILE_F (64 * LDG_)

template <int MODE>   // 0 = qkv, 1 = out-proj
__global__ __launch_bounds__(256) void gemm_w(const float* __restrict__ A,
                                              const float* __restrict__ Wq,
                                              const float* __restrict__ bq,
                                              const float* __restrict__ Wk,
                                              const float* __restrict__ bk,
                                              const float* __restrict__ Wv,
                                              const float* __restrict__ bv,
                                              const float* __restrict__ resid,
                                              float* __restrict__ Cq,
                                              float* __restrict__ Ck,
                                              float* __restrict__ Cv) {
    extern __shared__ float dsm[];
    float* Asb[2] = {dsm, dsm + TILE_F};
    float* Bsb[2] = {dsm + 2 * TILE_F, dsm + 3 * TILE_F};

    const int KTOT = (MODE == 1) ? 1536 : 256;
    const int KT = KTOT / 64;
    int tid = threadIdx.x;
    int warp = tid >> 5;
    int wm = warp & 3;
    int wn = warp >> 2;
    int m0 = blockIdx.y * 64, n0 = blockIdx.x * 64;

    const float* Bb;
    const float* bias;
    float* C;
    if (MODE == 0) {
        int z = blockIdx.z;
        int which = z / 6, zh = z - which * 6;
        Bb = ((which == 0) ? Wq : (which == 1) ? Wk : Wv) + (size_t)zh * 256 * 256;
        bias = ((which == 0) ? bq : (which == 1) ? bk : bv) + zh * 256;
        C = ((which == 0) ? Cq : (which == 1) ? Ck : Cv) + (size_t)zh * S * 256;
    } else {
        Bb = Wq;        // Wo
        bias = bq;      // bo
        C = Cq;         // ypre
    }

    // per-thread load slots (16 iterations of 16 threads... 256 thr x 16 jobs)
    auto issue_stage = [&](int kt, int buf) {
        unsigned int as = smem_u32g(Asb[buf]);
        unsigned int bs = smem_u32g(Bsb[buf]);
        int k0 = kt * 64;
        const float* Asrc;
        if (MODE == 1) {
            Asrc = A + (size_t)(k0 >> 8) * (S * 256) + (k0 & 255);
        } else {
            Asrc = A + k0;
        }
        for (int i = tid; i < 64 * 16; i += 256) {
            int m = i >> 4, k4 = i & 15;
            cp_async16g(as + (unsigned)(m * LDG_ + k4 * 4) * 4,
                        Asrc + (size_t)(m0 + m) * 256 + k4 * 4);
        }
        for (int i = tid; i < 64 * 16; i += 256) {
            int kk = i >> 4, n4 = i & 15;
            cp_async16g(bs + (unsigned)(kk * LDG_ + n4 * 4) * 4,
                        Bb + (size_t)(k0 + kk) * 256 + n0 + n4 * 4);
        }
        asm volatile("cp.async.commit_group;" ::: "memory");
    };

    wmma::fragment<wmma::accumulator, 16, 16, 8, float> c[2];
    wmma::fill_fragment(c[0], 0.0f);
    wmma::fill_fragment(c[1], 0.0f);

    issue_stage(0, 0);

    for (int kt = 0; kt < KT; kt++) {
        if (kt + 1 < KT) issue_stage(kt + 1, (kt + 1) & 1);
        if (kt + 1 < KT)
            asm volatile("cp.async.wait_group 1;" ::: "memory");
        else
            asm volatile("cp.async.wait_group 0;" ::: "memory");
        __syncthreads();

        float* As = Asb[kt & 1];
        float* Bs = Bsb[kt & 1];
        wmma::fragment<wmma::matrix_a, 16, 16, 8, wmma::precision::tf32,
                       wmma::row_major> af;
        wmma::fragment<wmma::matrix_b, 16, 16, 8, wmma::precision::tf32,
                       wmma::row_major> bf;
#pragma unroll
        for (int k = 0; k < 8; k++) {
            wmma::load_matrix_sync(af, As + (wm * 16) * LDG_ + k * 8, LDG_);
#pragma unroll
            for (int e = 0; e < af.num_elements; e++)
                af.x[e] = wmma::__float_to_tf32(af.x[e]);
#pragma unroll
            for (int nf = 0; nf < 2; nf++) {
                wmma::load_matrix_sync(
                    bf, Bs + (k * 8) * LDG_ + wn * 32 + nf * 16, LDG_);
#pragma unroll
                for (int e = 0; e < bf.num_elements; e++)
                    bf.x[e] = wmma::__float_to_tf32(bf.x[e]);
                wmma::mma_sync(c[nf], af, bf, c[nf]);
            }
        }
        __syncthreads();   // protect this buffer from the kt+2 issue
    }

#pragma unroll
    for (int nf = 0; nf < 2; nf++)
        wmma::store_matrix_sync(Asb[0] + (wm * 16) * LDG_ + wn * 32 + nf * 16,
                                c[nf], LDG_, wmma::mem_row_major);
    __syncthreads();

    for (int i = tid; i < 64 * 64; i += 256) {
        int m = i >> 6, n = i & 63;
        int gm = m0 + m, gn = n0 + n;
        float v = Asb[0][m * LDG_ + n] + bias[gn];
        if (MODE == 1) v += resid[(size_t)gm * 256 + gn];
        C[(size_t)gm * 256 + gn] = v;
    }
}

// ---------------- fp32 SIMT GEMM for gi = y @ W_ih^T + b_ih ------------------
__global__ __launch_bounds__(256) void gemm_gi(const float* __restrict__ A,
                                               const float* __restrict__ B,
                                               const float* __restrict__ bias,
                                               float* __restrict__ C) {
    __shared__ float As[64][65];
    __shared__ float Bs[64][65];
    int tid = threadIdx.x;
    int m0 = blockIdx.y * 64, n0 = blockIdx.x * 64;

    float acc[4][4];
#pragma unroll
    for (int i = 0; i < 4; i++)
#pragma unroll
        for (int j = 0; j < 4; j++) acc[i][j] = 0.f;

    int ty = tid >> 4, tx = tid & 15;

    for (int k0 = 0; k0 < 256; k0 += 64) {
#pragma unroll
        for (int i = 0; i < 16; i++) {
            int lin = i * 256 + tid;
            int m = lin >> 6, kk = lin & 63;
            As[m][kk] = A[(size_t)(m0 + m) * 256 + k0 + kk];
        }
#pragma unroll
        for (int i = 0; i < 16; i++) {
            int lin = i * 256 + tid;
            int n = lin >> 6, kk = lin & 63;
            Bs[kk][n] = B[(size_t)(n0 + n) * 256 + (k0 + kk)];
        }
        __syncthreads();
#pragma unroll 8
        for (int kk = 0; kk < 64; kk++) {
            float a[4], b[4];
#pragma unroll
            for (int i = 0; i < 4; i++) a[i] = As[ty * 4 + i][kk];
#pragma unroll
            for (int j = 0; j < 4; j++) b[j] = Bs[kk][tx * 4 + j];
#pragma unroll
            for (int i = 0; i < 4; i++)
#pragma unroll
                for (int j = 0; j < 4; j++) acc[i][j] += a[i] * b[j];
        }
        __syncthreads();
    }

#pragma unroll
    for (int i = 0; i < 4; i++) {
        int m = m0 + ty * 4 + i;
#pragma unroll
        for (int j = 0; j < 4; j++) {
            int n = n0 + tx * 4 + j;
            C[(size_t)m * 768 + n] = acc[i][j] + bias[n];
        }
    }
}

// ---------------- WMMA tf32 attention with cp.async pipelining ---------------
#define LDQ 268
#define LDP 76

__global__ __launch_bounds__(256) void attn_kernel(const float* __restrict__ Q,
                                                   const float* __restrict__ K,
                                                   const float* __restrict__ V,
                                                   float* __restrict__ O) {
    extern __shared__ float sm[];
    float* Qs = sm;
    float* Ks = Qs + 64 * LDQ;
    float* Vs = Ks + 64 * LDQ;
    float* Ps = Vs + 64 * LDQ;
    float* Ls = Ps + 64 * LDP;

    int h = blockIdx.y;
    int q0 = blockIdx.x * 64;
    int tid = threadIdx.x;
    int warp = tid >> 5;
    int wm = warp & 3;
    int wn = warp >> 2;

    const float* Qg = Q + ((size_t)h * S + q0) * H;
    const float* Kg = K + (size_t)h * S * H;
    const float* Vg = V + (size_t)h * S * H;

    unsigned int ks_base = smem_u32g(Ks);
    unsigned int vs_base = smem_u32g(Vs);

    for (int i = tid; i < 64 * 64; i += 256) {
        int r = i >> 6, d4 = i & 63;
        cp_async16g(ks_base + (unsigned)(r * LDQ + d4 * 4) * 4,
                    Kg + (size_t)r * H + d4 * 4);
    }
    asm volatile("cp.async.commit_group;" ::: "memory");

    for (int i = tid; i < 64 * 64; i += 256) {
        int q = i >> 6, d4 = i & 63;
        ((float4*)(Qs + q * LDQ))[d4] = ((const float4*)(Qg + (size_t)q * H))[d4];
    }

    wmma::fragment<wmma::accumulator, 16, 16, 8, float> o_frag[8];
#pragma unroll
    for (int f = 0; f < 8; f++) wmma::fill_fragment(o_frag[f], 0.0f);

    int lrow = tid >> 2;
    int lcol0 = (tid & 3) * 16;
    float l_part = 0.f;
    const float inv_scale = 0.0625f;

    for (int kt = 0; kt < S / 64; kt++) {
        asm volatile("cp.async.wait_group 0;" ::: "memory");
        __syncthreads();

        for (int i = tid; i < 64 * 64; i += 256) {
            int r = i >> 6, d4 = i & 63;
            cp_async16g(vs_base + (unsigned)(r * LDQ + d4 * 4) * 4,
                        Vg + (size_t)(kt * 64 + r) * H + d4 * 4);
        }
        asm volatile("cp.async.commit_group;" ::: "memory");

        {
            wmma::fragment<wmma::matrix_a, 16, 16, 8, wmma::precision::tf32,
                           wmma::row_major> af;
            wmma::fragment<wmma::matrix_b, 16, 16, 8, wmma::precision::tf32,
                           wmma::col_major> bf;
            wmma::fragment<wmma::accumulator, 16, 16, 8, float> c[2];
            wmma::fill_fragment(c[0], 0.0f);
            wmma::fill_fragment(c[1], 0.0f);
#pragma unroll 4
            for (int k = 0; k < 32; k++) {
                wmma::load_matrix_sync(af, Qs + (wm * 16) * LDQ + k * 8, LDQ);
#pragma unroll
                for (int e = 0; e < af.num_elements; e++)
                    af.x[e] = wmma::__float_to_tf32(af.x[e]);
#pragma unroll
                for (int nf = 0; nf < 2; nf++) {
                    wmma::load_matrix_sync(
                        bf, Ks + (wn * 32 + nf * 16) * LDQ + k * 8, LDQ);
#pragma unroll
                    for (int e = 0; e < bf.num_elements; e++)
                        bf.x[e] = wmma::__float_to_tf32(bf.x[e]);
                    wmma::mma_sync(c[nf], af, bf, c[nf]);
                }
            }
#pragma unroll
            for (int nf = 0; nf < 2; nf++)
                wmma::store_matrix_sync(
                    Ps + (wm * 16) * LDP + wn * 32 + nf * 16, c[nf], LDP,
                    wmma::mem_row_major);
        }
        __syncthreads();

        {
            int ktn = (kt + 1 < S / 64) ? (kt + 1) : kt;
            for (int i = tid; i < 64 * 64; i += 256) {
                int r = i >> 6, d4 = i & 63;
                cp_async16g(ks_base + (unsigned)(r * LDQ + d4 * 4) * 4,
                            Kg + (size_t)(ktn * 64 + r) * H + d4 * 4);
            }
            asm volatile("cp.async.commit_group;" ::: "memory");
        }

        {
            float* pr = Ps + lrow * LDP + lcol0;
            float ssum = 0.f;
#pragma unroll
            for (int j = 0; j < 16; j++) {
                float e = __expf(pr[j] * inv_scale);
                pr[j] = e;
                ssum += e;
            }
            l_part += ssum;
        }

        asm volatile("cp.async.wait_group 1;" ::: "memory");
        __syncthreads();

        {
            wmma::fragment<wmma::matrix_a, 16, 16, 8, wmma::precision::tf32,
                           wmma::row_major> pa;
            wmma::fragment<wmma::matrix_b, 16, 16, 8, wmma::precision::tf32,
                           wmma::row_major> vb;
#pragma unroll
            for (int k = 0; k < 8; k++) {
                wmma::load_matrix_sync(pa, Ps + (wm * 16) * LDP + k * 8, LDP);
#pragma unroll
                for (int e = 0; e < pa.num_elements; e++)
                    pa.x[e] = wmma::__float_to_tf32(pa.x[e]);
#pragma unroll
                for (int nf = 0; nf < 8; nf++) {
                    wmma::load_matrix_sync(
                        vb, Vs + (k * 8) * LDQ + wn * 128 + nf * 16, LDQ);
#pragma unroll
                    for (int e = 0; e < vb.num_elements; e++)
                        vb.x[e] = wmma::__float_to_tf32(vb.x[e]);
                    wmma::mma_sync(o_frag[nf], pa, vb, o_frag[nf]);
                }
            }
        }
    }

    l_part += __shfl_xor_sync(0xffffffffu, l_part, 1);
    l_part += __shfl_xor_sync(0xffffffffu, l_part, 2);
    if ((tid & 3) == 0) Ls[lrow] = l_part;

#pragma unroll
    for (int nf = 0; nf < 8; nf++)
        wmma::store_matrix_sync(Qs + (wm * 16) * LDQ + wn * 128 + nf * 16,
                                o_frag[nf], LDQ, wmma::mem_row_major);
    __syncthreads();

    float* Og = O + ((size_t)h * S + q0) * H;
    for (int i = tid; i < 64 * 64; i += 256) {
        int q = i >> 6, d4 = i & 63;
        float inv_l = __frcp_rn(Ls[q]);
        float4 v = ((float4*)(Qs + q * LDQ))[d4];
        v.x *= inv_l; v.y *= inv_l; v.z *= inv_l; v.w *= inv_l;
        ((float4*)(Og + (size_t)q * H))[d4] = v;
    }
}

// ---------------- LayerNorm (one warp per row) ----------------
__global__ __launch_bounds__(256) void ln_kernel(const float* __restrict__ yin,
                                                 const float* __restrict__ g,
                                                 const float* __restrict__ b,
                                                 float* __restrict__ yout) {
    int row = blockIdx.x * 8 + (threadIdx.x >> 5);
    int lane = threadIdx.x & 31;
    const float* yr = yin + (size_t)row * H;
    float v[8], s = 0.f, sq = 0.f;
#pragma unroll
    for (int i = 0; i < 8; i++) {
        v[i] = yr[lane + i * 32];
        s += v[i];
        sq += v[i] * v[i];
    }
#pragma unroll
    for (int m = 16; m >= 1; m >>= 1) {
        s += __shfl_xor_sync(0xffffffffu, s, m);
        sq += __shfl_xor_sync(0xffffffffu, sq, m);
    }
    float mu = s * (1.f / H);
    float var = sq * (1.f / H) - mu * mu;
    float rstd = rsqrtf(var + EPS);
    float* yo = yout + (size_t)row * H;
#pragma unroll
    for (int i = 0; i < 8; i++) {
        int c = lane + i * 32;
        yo[c] = (v[i] - mu) * rstd * g[c] + b[c];
    }
}

// ---------------- GRU recurrence: 8-CTA cluster, 16B-packet st.async ---------
#define RB 8
#define RT 256

__device__ __forceinline__ unsigned int smem_u32(const void* p) {
    unsigned int a;
    asm("{ .reg .u64 t; cvta.to.shared.u64 t, %1; cvt.u32.u64 %0, t; }"
        : "=r"(a) : "l"(p));
    return a;
}

__device__ __forceinline__ void cluster_arrive_wait() {
    asm volatile("barrier.cluster.arrive.aligned;" ::: "memory");
    asm volatile("barrier.cluster.wait.aligned;" ::: "memory");
}

__device__ __forceinline__ void mbar_wait_parity(unsigned int mb,
                                                 unsigned int parity) {
    asm volatile(
        "{\n\t"
        ".reg .pred P;\n\t"
        "WL%=:\n\t"
        "mbarrier.try_wait.parity.acquire.cta.shared::cta.b64 P, [%0], %1, 0x989680;\n\t"
        "@!P bra WL%=;\n\t"
        "}"
        :: "r"(mb), "r"(parity) : "memory");
}

__global__ void __cluster_dims__(RB, 1, 1) __launch_bounds__(RT, 1)
rnn_kernel(const float* __restrict__ gi,
           const float* __restrict__ Whh,
           const float* __restrict__ bhh,
           float* __restrict__ out,
           int out_size) {
    __shared__ __align__(16) float hbuf[2][H];
    __shared__ __align__(8) unsigned long long mbar[2];

    int blk = blockIdx.x;
    int tid = threadIdx.x;
    int w = tid >> 5;
    int lane = tid & 31;

    unsigned long long w2[12][4];
#pragma unroll
    for (int g = 0; g < 3; g++) {
#pragma unroll
        for (int dd = 0; dd < 4; dd++) {
            int rowg = g * 256 + blk * 32 + w * 4 + dd;
            const unsigned long long* src =
                (const unsigned long long*)(Whh + (size_t)rowg * H + lane * 8);
#pragma unroll
            for (int i = 0; i < 4; i++) w2[g * 4 + dd][i] = src[i];
        }
    }

    for (int i = tid; i < 2 * H; i += RT) ((float*)hbuf)[i] = 0.f;

    unsigned int mb0 = smem_u32(&mbar[0]);
    unsigned int mb1 = smem_u32(&mbar[1]);
    if (tid == 0) {
        asm volatile("mbarrier.init.shared.b64 [%0], %1;"
                     :: "r"(mb0), "r"(1) : "memory");
        asm volatile("mbarrier.init.shared.b64 [%0], %1;"
                     :: "r"(mb1), "r"(1) : "memory");
        asm volatile("mbarrier.arrive.expect_tx.shared.b64 _, [%0], %1;"
                     :: "r"(mb0), "r"(1024) : "memory");
        asm volatile("mbarrier.arrive.expect_tx.shared.b64 _, [%0], %1;"
                     :: "r"(mb1), "r"(1024) : "memory");
    }

    int d = w * 4 + lane;
    int j = blk * 32 + d;
    int jc = j & 255;
    bool owner = (lane < 4);
    float ir = 0.f, iz = 0.f, inn = 0.f, bh_r = 0.f, bh_z = 0.f, bh_n = 0.f;
    if (owner) {
        ir = gi[j];
        iz = gi[256 + j];
        inn = gi[512 + j];
        bh_r = bhh[j];
        bh_z = bhh[256 + j];
        bh_n = bhh[512 + j];
    }
    unsigned int hb0 = smem_u32(&hbuf[0][lane * 8]);
    unsigned int hb1 = smem_u32(&hbuf[1][lane * 8]);

    unsigned int wl0 = smem_u32(&hbuf[0][blk * 32 + w * 4]);
    unsigned int wl1 = smem_u32(&hbuf[1][blk * 32 + w * 4]);
    int rr = lane & 7;
    unsigned int pdst0, pdst1, pmb0, pmb1;
    asm("mapa.shared::cluster.u32 %0, %1, %2;" : "=r"(pdst0) : "r"(wl0), "r"(rr));
    asm("mapa.shared::cluster.u32 %0, %1, %2;" : "=r"(pdst1) : "r"(wl1), "r"(rr));
    asm("mapa.shared::cluster.u32 %0, %1, %2;" : "=r"(pmb0) : "r"(mb0), "r"(rr));
    asm("mapa.shared::cluster.u32 %0, %1, %2;" : "=r"(pmb1) : "r"(mb1), "r"(rr));

    __syncthreads();
    cluster_arrive_wait();

    for (int t = 0; t < S; t++) {
        int p = t & 1;

        unsigned int haddr = p ? hb1 : hb0;
        unsigned long long h2[4];
        asm volatile("ld.shared.v2.b64 {%0, %1}, [%4];\n\t"
                     "ld.shared.v2.b64 {%2, %3}, [%4 + 16];"
                     : "=l"(h2[0]), "=l"(h2[1]), "=l"(h2[2]), "=l"(h2[3])
                     : "r"(haddr));
        float a[12];
#pragma unroll
        for (int r = 0; r < 12; r++) {
            unsigned long long acc2 = 0ull;
#pragma unroll
            for (int i = 0; i < 4; i++) {
                asm("fma.rn.f32x2 %0, %1, %2, %0;"
                    : "+l"(acc2) : "l"(w2[r][i]), "l"(h2[i]));
            }
            float lo, hi;
            asm("mov.b64 {%0, %1}, %2;" : "=f"(lo), "=f"(hi) : "l"(acc2));
            a[r] = lo + hi;
        }

        int l0 = lane & 1;
        int l1 = (lane >> 1) & 1;
        float b6[6];
#pragma unroll
        for (int g = 0; g < 3; g++) {
#pragma unroll
            for (int d1 = 0; d1 < 2; d1++) {
                float x = a[g * 4 + (d1 << 1) + 0];
                float y = a[g * 4 + (d1 << 1) + 1];
                float keep = l0 ? y : x;
                float send = l0 ? x : y;
                b6[g * 2 + d1] = keep + __shfl_xor_sync(0xffffffffu, send, 1);
            }
        }
        float z3[3];
#pragma unroll
        for (int g = 0; g < 3; g++) {
            float x = b6[g * 2 + 0];
            float y = b6[g * 2 + 1];
            float keep = l1 ? y : x;
            float send = l1 ? x : y;
            z3[g] = keep + __shfl_xor_sync(0xffffffffu, send, 2);
        }
#pragma unroll
        for (int m = 4; m <= 16; m <<= 1) {
#pragma unroll
            for (int g = 0; g < 3; g++)
                z3[g] += __shfl_xor_sync(0xffffffffu, z3[g], m);
        }

        float ghr = z3[0] + bh_r;
        float ghz = z3[1] + bh_z;
        float ghn = z3[2] + bh_n;
        float hold = hbuf[p][jc];
        float r = 1.f / (1.f + __expf(-(ir + ghr)));
        float z = 1.f / (1.f + __expf(-(iz + ghz)));
        float narg = inn + r * ghn;
        float n = 1.f - 2.f / (1.f + __expf(2.f * narg));
        float hnew = (1.f - z) * n + z * hold;

        float b0 = __shfl_sync(0xffffffffu, hnew, 0);
        float b1 = __shfl_sync(0xffffffffu, hnew, 1);
        float b2 = __shfl_sync(0xffffffffu, hnew, 2);
        float b3 = __shfl_sync(0xffffffffu, hnew, 3);

        if (lane < 8) {
            unsigned int pd = p ? pdst0 : pdst1;
            unsigned int pm = p ? pmb1 : pmb0;
            asm volatile(
                "st.async.shared::cluster.mbarrier::complete_tx::bytes.v4.b32 "
                "[%0], {%1, %2, %3, %4}, [%5];"
                :: "r"(pd), "f"(b0), "f"(b1), "f"(b2), "f"(b3), "r"(pm)
                : "memory");
        }

        if (owner) {
            int tn = (t + 1 < S) ? (t + 1) : t;
            ir = gi[(size_t)tn * G3 + j];
            iz = gi[(size_t)tn * G3 + 256 + j];
            inn = gi[(size_t)tn * G3 + 512 + j];
        }

        unsigned int mbp = p ? mb1 : mb0;
        if (lane == 0) {
            mbar_wait_parity(mbp, (unsigned int)((t >> 1) & 1));
            if (tid == 0) {
                asm volatile("mbarrier.arrive.expect_tx.shared.b64 _, [%0], %1;"
                             :: "r"(mbp), "r"(1024) : "memory");
            }
        }
        __syncwarp();
    }

    if (blk == 0) {
        for (int i = tid; i < out_size; i += RT)
            out[i] = hbuf[0][i & 255];
    }
}

// ---------------- host launcher ----------------
extern "C" void kernel_launch(void* const* d_in, const int* in_sizes, int n_in,
                              void* d_out, int out_size) {
    const int* tokens = (const int*)d_in[0];
    const float* emb = (const float*)d_in[1];
    const float* Wq = (const float*)d_in[2];
    const float* bq = (const float*)d_in[3];
    const float* Wk = (const float*)d_in[4];
    const float* bk = (const float*)d_in[5];
    const float* Wv = (const float*)d_in[6];
    const float* bv = (const float*)d_in[7];
    const float* Wo = (const float*)d_in[8];
    const float* bo = (const float*)d_in[9];
    const float* ln_g = (const float*)d_in[10];
    const float* ln_b = (const float*)d_in[11];
    const float* W_ih = (const float*)d_in[12];
    const float* W_hh = (const float*)d_in[13];
    const float* b_ih = (const float*)d_in[14];
    const float* b_hh = (const float*)d_in[15];
    float* out = (float*)d_out;

    float* px; cudaGetSymbolAddress((void**)&px, g_x);
    float* pq; cudaGetSymbolAddress((void**)&pq, g_q);
    float* pk; cudaGetSymbolAddress((void**)&pk, g_k);
    float* pv; cudaGetSymbolAddress((void**)&pv, g_v);
    float* po; cudaGetSymbolAddress((void**)&po, g_o);
    float* pypre; cudaGetSymbolAddress((void**)&pypre, g_ypre);
    float* py; cudaGetSymbolAddress((void**)&py, g_y);
    float* pgi; cudaGetSymbolAddress((void**)&pgi, g_gi);

    size_t attn_smem = (size_t)(3 * 64 * LDQ + 64 * LDP + 64) * sizeof(float);
    cudaFuncSetAttribute(attn_kernel, cudaFuncAttributeMaxDynamicSharedMemorySize,
                         (int)attn_smem);
    size_t gemm_smem = (size_t)(4 * TILE_F) * sizeof(float);
    cudaFuncSetAttribute(gemm_w<0>, cudaFuncAttributeMaxDynamicSharedMemorySize,
                         (int)gemm_smem);
    cudaFuncSetAttribute(gemm_w<1>, cudaFuncAttributeMaxDynamicSharedMemorySize,
                         (int)gemm_smem);

    embed_kernel<<<S, 64>>>(tokens, emb);

    dim3 gqkv(4, 64, 3 * NH);
    gemm_w<0><<<gqkv, 256, gemm_smem>>>(px, Wq, bq, Wk, bk, Wv, bv, nullptr,
                                        pq, pk, pv);

    dim3 gatt(S / 64, NH);
    attn_kernel<<<gatt, 256, attn_smem>>>(pq, pk, pv, po);

    dim3 gop(4, 64, 1);
    gemm_w<1><<<gop, 256, gemm_smem>>>(po, Wo, bo, nullptr, nullptr, nullptr,
                                       nullptr, px, pypre, nullptr, nullptr);

    ln_kernel<<<S / 8, 256>>>(pypre, ln_g, ln_b, py);

    dim3 ggi(12, 64, 1);
    gemm_gi<<<ggi, 256>>>(py, W_ih, b_ih, pgi);

    rnn_kernel<<<RB, RT>>>(pgi, W_hh, b_hh, out, out_size);
}